// round 9
// baseline (speedup 1.0000x reference)
#include <cuda_runtime.h>
#include <cuda_bf16.h>

// Problem: cummax along axis=2 of x[B=8, Tt=128, Ts=128, C=512] fp32.
// out[b,t,j,c] = max_{j'<=j} x[b,t,j',c]
//
// R8: R7 config (1024 CTAs x 128 threads, one CTA per (b,t) row, float4,
// unroll 8) + __ldlu on the READ stream only. ld.global.lu marks each input
// line last-use -> invalidate after read, freeing L2 ways for the store
// stream's write coalescing. Stores keep default policy (R3 showed evict-
// first on partially-assembled store lines fragments DRAM writebacks).

static __device__ __forceinline__ float4 f4max(float4 a, float4 b) {
    float4 r;
    r.x = fmaxf(a.x, b.x);
    r.y = fmaxf(a.y, b.y);
    r.z = fmaxf(a.z, b.z);
    r.w = fmaxf(a.w, b.w);
    return r;
}

// One CTA per (b,t) row: 128 threads cover the 128 float4 channel groups.
// Each thread walks j = 0..127 (stride 2KB) with a register running max.
__global__ void __launch_bounds__(128) cummax_kernel(
    const float4* __restrict__ in, float4* __restrict__ out)
{
    constexpr int TS = 128;
    constexpr int C4 = 128;               // 512 channels / 4
    const int bt = blockIdx.x;            // (b,t) row, 0..1023
    const int c4 = threadIdx.x;           // float4 within C, 0..127

    const float4* __restrict__ p = in  + (size_t)bt * TS * C4 + c4;
    float4* __restrict__       q = out + (size_t)bt * TS * C4 + c4;

    float4 m = __ldlu(p);
    q[0] = m;

    #pragma unroll 8
    for (int j = 1; j < TS; ++j) {
        float4 v = __ldlu(p + (size_t)j * C4);
        m = f4max(m, v);
        q[(size_t)j * C4] = m;
    }
}

extern "C" void kernel_launch(void* const* d_in, const int* in_sizes, int n_in,
                              void* d_out, int out_size)
{
    const float4* x = (const float4*)d_in[0];
    float4* y = (float4*)d_out;

    // 1024 CTAs = B*Tt rows; 128 threads = C/4 float4 columns per row.
    cummax_kernel<<<1024, 128>>>(x, y);
}

// round 10
// speedup vs baseline: 1.0250x; 1.0250x over previous
#include <cuda_runtime.h>
#include <cuda_bf16.h>

// Problem: cummax along axis=2 of x[B=8, Tt=128, Ts=128, C=512] fp32.
// out[b,t,j,c] = max_{j'<=j} x[b,t,j',c]
//
// R9: 256-bit global accesses (PTX ISA 8.8, sm_100+ family: ld/st.global.v8.f32).
// Halves LDG/STG instruction count, doubles per-request granularity (32B/lane,
// 1KB contiguous per warp per j-step). Geometry keeps R7's balance win:
// 1024 CTAs (7-vs-6 CTAs/SM) x 64 threads; one CTA per (b,t) row,
// each thread owns 8 channels. NO cache hints (three regressions traced
// to hint intrinsics breaking ptxas load batching).

__global__ void __launch_bounds__(64) cummax_kernel(
    const float* __restrict__ in, float* __restrict__ out)
{
    constexpr int TS = 128;
    constexpr int C  = 512;
    const int bt = blockIdx.x;            // (b,t) row, 0..1023
    const int c8 = threadIdx.x;           // 8-float group, 0..63

    const float* __restrict__ p = in  + (size_t)bt * TS * C + (size_t)c8 * 8;
    float* __restrict__       q = out + (size_t)bt * TS * C + (size_t)c8 * 8;

    float m0, m1, m2, m3, m4, m5, m6, m7;
    asm volatile(
        "ld.global.v8.f32 {%0,%1,%2,%3,%4,%5,%6,%7}, [%8];"
        : "=f"(m0), "=f"(m1), "=f"(m2), "=f"(m3),
          "=f"(m4), "=f"(m5), "=f"(m6), "=f"(m7)
        : "l"(p));
    asm volatile(
        "st.global.v8.f32 [%0], {%1,%2,%3,%4,%5,%6,%7,%8};"
        :: "l"(q),
           "f"(m0), "f"(m1), "f"(m2), "f"(m3),
           "f"(m4), "f"(m5), "f"(m6), "f"(m7)
        : "memory");

    #pragma unroll 4
    for (int j = 1; j < TS; ++j) {
        const float* pj = p + (size_t)j * C;
        float* qj       = q + (size_t)j * C;
        float v0, v1, v2, v3, v4, v5, v6, v7;
        asm volatile(
            "ld.global.v8.f32 {%0,%1,%2,%3,%4,%5,%6,%7}, [%8];"
            : "=f"(v0), "=f"(v1), "=f"(v2), "=f"(v3),
              "=f"(v4), "=f"(v5), "=f"(v6), "=f"(v7)
            : "l"(pj));
        m0 = fmaxf(m0, v0); m1 = fmaxf(m1, v1);
        m2 = fmaxf(m2, v2); m3 = fmaxf(m3, v3);
        m4 = fmaxf(m4, v4); m5 = fmaxf(m5, v5);
        m6 = fmaxf(m6, v6); m7 = fmaxf(m7, v7);
        asm volatile(
            "st.global.v8.f32 [%0], {%1,%2,%3,%4,%5,%6,%7,%8};"
            :: "l"(qj),
               "f"(m0), "f"(m1), "f"(m2), "f"(m3),
               "f"(m4), "f"(m5), "f"(m6), "f"(m7)
            : "memory");
    }
}

extern "C" void kernel_launch(void* const* d_in, const int* in_sizes, int n_in,
                              void* d_out, int out_size)
{
    const float* x = (const float*)d_in[0];
    float* y = (float*)d_out;

    // 1024 CTAs = B*Tt rows; 64 threads x 8 floats = 512 channels per row.
    cummax_kernel<<<1024, 64>>>(x, y);
}

// round 11
// speedup vs baseline: 1.1983x; 1.1691x over previous
#include <cuda_runtime.h>
#include <cuda_bf16.h>
#include <math_constants.h>
#include <cstdint>

// Problem: cummax along axis=2 of x[B=8, Tt=128, Ts=128, C=512] fp32.
// out[b,t,j,c] = max_{j'<=j} x[b,t,j',c]
//
// R10: bulk-copy pipeline. A tile of 4 consecutive j-steps x 512 channels is
// 8KB CONTIGUOUS in gmem for one (b,t) row. One CTA per row:
//   cp.async.bulk (gmem->smem, mbarrier complete_tx, double-buffered)
//   -> 128 threads running-max through smem (conflict-free 16B/lane)
//   -> cp.async.bulk (smem->gmem, bulk_group, double-buffered).
// DRAM requests become 8KB sequential bursts (page locality) instead of
// 16B/lane fragments from ~28 interleaved warps.

constexpr int THREADS = 128;
constexpr int TS      = 128;
constexpr int C4      = 128;          // 512 channels / 4 floats
constexpr int JT      = 4;            // j-steps per tile
constexpr int NT      = TS / JT;      // 32 tiles
constexpr int TILE_B  = JT * C4 * 16; // 8192 bytes

__global__ void __launch_bounds__(THREADS) cummax_kernel(
    const float4* __restrict__ in, float4* __restrict__ out)
{
    __shared__ alignas(128) float4 inb [2][JT][THREADS];   // 16 KB
    __shared__ alignas(128) float4 outb[2][JT][THREADS];   // 16 KB
    __shared__ alignas(8) unsigned long long mbar[2];

    const int tid = threadIdx.x;
    const int bt  = blockIdx.x;                 // (b,t) row, 0..1023

    const char* gsrc = (const char*)(in  + (size_t)bt * TS * C4);
    char*       gdst = (char*)      (out + (size_t)bt * TS * C4);

    const uint32_t s_in0  = (uint32_t)__cvta_generic_to_shared(&inb[0][0][0]);
    const uint32_t s_in1  = (uint32_t)__cvta_generic_to_shared(&inb[1][0][0]);
    const uint32_t s_out0 = (uint32_t)__cvta_generic_to_shared(&outb[0][0][0]);
    const uint32_t s_out1 = (uint32_t)__cvta_generic_to_shared(&outb[1][0][0]);
    const uint32_t s_mb0  = (uint32_t)__cvta_generic_to_shared(&mbar[0]);
    const uint32_t s_mb1  = (uint32_t)__cvta_generic_to_shared(&mbar[1]);

    if (tid == 0) {
        asm volatile("mbarrier.init.shared.b64 [%0], 1;" :: "r"(s_mb0) : "memory");
        asm volatile("mbarrier.init.shared.b64 [%0], 1;" :: "r"(s_mb1) : "memory");
        asm volatile("fence.proxy.async.shared::cta;" ::: "memory");
    }
    __syncthreads();   // mbarrier init visible to all threads before any wait

    if (tid == 0) {
        // Prime: bulk-load tiles 0 and 1.
        asm volatile("mbarrier.arrive.expect_tx.shared.b64 _, [%0], %1;"
                     :: "r"(s_mb0), "r"(TILE_B) : "memory");
        asm volatile("cp.async.bulk.shared::cluster.global.mbarrier::complete_tx::bytes"
                     " [%0], [%1], %2, [%3];"
                     :: "r"(s_in0), "l"(gsrc), "r"(TILE_B), "r"(s_mb0) : "memory");
        asm volatile("mbarrier.arrive.expect_tx.shared.b64 _, [%0], %1;"
                     :: "r"(s_mb1), "r"(TILE_B) : "memory");
        asm volatile("cp.async.bulk.shared::cluster.global.mbarrier::complete_tx::bytes"
                     " [%0], [%1], %2, [%3];"
                     :: "r"(s_in1), "l"(gsrc + TILE_B), "r"(TILE_B), "r"(s_mb1) : "memory");
    }

    float4 m = make_float4(-CUDART_INF_F, -CUDART_INF_F,
                           -CUDART_INF_F, -CUDART_INF_F);
    int ph0 = 0, ph1 = 0;

    #pragma unroll 1
    for (int t = 0; t < NT; ++t) {
        const int s = t & 1;
        const uint32_t mb   = s ? s_mb1  : s_mb0;
        const uint32_t sout = s ? s_out1 : s_out0;
        const uint32_t sin  = s ? s_in1  : s_in0;
        const int par = s ? ph1 : ph0;
        if (s) ph1 ^= 1; else ph0 ^= 1;

        // 1. Wait for this tile's bulk load (acquire: generic LDS follows).
        asm volatile(
            "{\n\t.reg .pred P;\n"
            "LW%=:\n\t"
            "mbarrier.try_wait.parity.acquire.cta.shared::cta.b64 P, [%0], %1, 0x989680;\n\t"
            "@P bra LD%=;\n\t"
            "bra LW%=;\n"
            "LD%=:\n\t}"
            :: "r"(mb), "r"(par) : "memory");

        // 2. Free this out-buffer: bulk store from tile t-2 must have
        //    finished READING smem before compute overwrites it.
        if (t >= 2 && tid == 0)
            asm volatile("cp.async.bulk.wait_group.read 1;" ::: "memory");
        __syncthreads();

        // 3. Compute: running max through smem (conflict-free 16B/lane).
        #pragma unroll
        for (int u = 0; u < JT; ++u) {
            float4 v = inb[s][u][tid];
            m.x = fmaxf(m.x, v.x);
            m.y = fmaxf(m.y, v.y);
            m.z = fmaxf(m.z, v.z);
            m.w = fmaxf(m.w, v.w);
            outb[s][u][tid] = m;
        }
        __syncthreads();   // all LDS of inb[s] + all STS of outb[s] done

        // 4. One thread: bulk-store this tile; refill inb[s] with tile t+2.
        if (tid == 0) {
            asm volatile("fence.proxy.async.shared::cta;" ::: "memory");
            asm volatile("cp.async.bulk.global.shared::cta.bulk_group [%0], [%1], %2;"
                         :: "l"(gdst + (size_t)t * TILE_B), "r"(sout), "r"(TILE_B)
                         : "memory");
            asm volatile("cp.async.bulk.commit_group;" ::: "memory");

            const int tn = t + 2;
            if (tn < NT) {
                asm volatile("mbarrier.arrive.expect_tx.shared.b64 _, [%0], %1;"
                             :: "r"(mb), "r"(TILE_B) : "memory");
                asm volatile("cp.async.bulk.shared::cluster.global.mbarrier::complete_tx::bytes"
                             " [%0], [%1], %2, [%3];"
                             :: "r"(sin), "l"(gsrc + (size_t)tn * TILE_B),
                                "r"(TILE_B), "r"(mb) : "memory");
            }
        }
    }

    // Drain outstanding bulk stores before exit.
    if (tid == 0)
        asm volatile("cp.async.bulk.wait_group 0;" ::: "memory");
}

extern "C" void kernel_launch(void* const* d_in, const int* in_sizes, int n_in,
                              void* d_out, int out_size)
{
    const float4* x = (const float4*)d_in[0];
    float4* y = (float4*)d_out;

    // 1024 CTAs = B*Tt rows; 128 threads; 32 KB static smem -> 7 CTAs/SM.
    cummax_kernel<<<1024, THREADS>>>(x, y);
}